// round 8
// baseline (speedup 1.0000x reference)
#include <cuda_runtime.h>
#include <cuda_bf16.h>
#include <cstdint>

#define BATCH 8
#define CH    512
#define DD    64
#define NN    4096
#define EPSF  1e-10f

typedef unsigned long long ull;

// ---------------- scratch (__device__ globals; no allocs allowed) ----------
__device__ __align__(16) __nv_bfloat16 g_Wh[128 * CH];   // stacked wq/wk hi, [m][k] row-major
__device__ __align__(16) __nv_bfloat16 g_Wl[128 * CH];   // lo residual
__device__ __align__(16) __nv_bfloat16 g_Qh[BATCH * DD * NN];  // delu(Q) hi, [b][d][n]
__device__ __align__(16) __nv_bfloat16 g_Ql[BATCH * DD * NN];  // delu(Q) lo residual
__device__ float g_KXt[BATCH * DD * CH];   // Kf @ x^T (atomic accum)
__device__ float g_KV[BATCH * DD * CH];    // KXt @ wv^T + bias (atomic accum)
__device__ float g_Ksum[BATCH * DD];       // EPS + sum_n Kf

__device__ __forceinline__ float delu(float v) {
    return 10.0f * fmaxf(v, 0.0f) + __expf(10.0f * fminf(v, 0.0f));
}

// ---------------- cp.async ----------
__device__ __forceinline__ void cpa16(uint32_t dst, const void* src) {
    asm volatile("cp.async.cg.shared.global [%0], [%1], 16;" :: "r"(dst), "l"(src));
}
__device__ __forceinline__ void cp_commit() { asm volatile("cp.async.commit_group;" ::: "memory"); }
__device__ __forceinline__ void cp_wait0()  { asm volatile("cp.async.wait_group 0;" ::: "memory"); }
__device__ __forceinline__ uint32_t sm_u32(const void* p) {
    return (uint32_t)__cvta_generic_to_shared(p);
}

// ---------------- mma.sync bf16 helpers ----------
__device__ __forceinline__ void ldsm4(uint32_t& r0, uint32_t& r1, uint32_t& r2, uint32_t& r3,
                                      uint32_t addr) {
    asm volatile("ldmatrix.sync.aligned.m8n8.x4.shared.b16 {%0,%1,%2,%3}, [%4];"
                 : "=r"(r0), "=r"(r1), "=r"(r2), "=r"(r3) : "r"(addr));
}
__device__ __forceinline__ void ldsm4t(uint32_t& r0, uint32_t& r1, uint32_t& r2, uint32_t& r3,
                                       uint32_t addr) {
    asm volatile("ldmatrix.sync.aligned.m8n8.x4.trans.shared.b16 {%0,%1,%2,%3}, [%4];"
                 : "=r"(r0), "=r"(r1), "=r"(r2), "=r"(r3) : "r"(addr));
}
__device__ __forceinline__ void mma16816(float* c, uint32_t a0, uint32_t a1, uint32_t a2,
                                         uint32_t a3, uint32_t b0, uint32_t b1) {
    asm volatile("mma.sync.aligned.m16n8k16.row.col.f32.bf16.bf16.f32 "
                 "{%0,%1,%2,%3},{%4,%5,%6,%7},{%8,%9},{%0,%1,%2,%3};"
                 : "+f"(c[0]), "+f"(c[1]), "+f"(c[2]), "+f"(c[3])
                 : "r"(a0), "r"(a1), "r"(a2), "r"(a3), "r"(b0), "r"(b1));
}

// smem byte offsets (qk_kxt kernel). Pitch 136 halves (272 B) for mma tiles.
#define XS_OFF   0         // staging x [128k][132n] float = 67584 B ; phase2 Xs; Kf_s region below
#define AH_OFF   67584     // Ah [128m][136k] bf16 = 34816 B   (Kf_s [64][132] floats reuses this)
#define AL_OFF   102400
#define BH_OFF   137216    // Bh [128n][136k] bf16
#define BL_OFF   172032
#define SMEM_TOT 206848

// out_kernel smem byte offsets
#define O_QH   0           // [64 d][136 n] bf16 = 17408 B
#define O_QL   17408
#define O_AH   34816       // [128 c][72 d] bf16 = 18432 B
#define O_AL   53248
#define O_KS   71680       // [64] float
#define O_NV   71936       // [128] float
#define O_SMEM 72448

// ---------------------------------------------------------------------------
// 0) init: zero accumulators, Ksum = EPS, split W into bf16 hi/lo panels
// ---------------------------------------------------------------------------
__global__ void init_kernel(const float* __restrict__ wq, const float* __restrict__ wk) {
    int i = blockIdx.x * blockDim.x + threadIdx.x;
    if (i < BATCH * DD * CH) { g_KXt[i] = 0.0f; g_KV[i] = 0.0f; }
    if (i < BATCH * DD) g_Ksum[i] = EPSF;
    if (i < 128 * CH) {
        int m = i >> 9, k = i & 511;
        float w = (m < 64) ? wq[(size_t)m * CH + k] : wk[(size_t)(m - 64) * CH + k];
        __nv_bfloat16 h = __float2bfloat16_rn(w);
        __nv_bfloat16 l = __float2bfloat16_rn(w - __bfloat162float(h));
        g_Wh[i] = h;
        g_Wl[i] = l;
    }
}

// ---------------------------------------------------------------------------
// 1) FUSED: Q/K projection via mma.sync bf16-split + delu + Ksum + KXt (FFMA).
//    grid = (NN/128, BATCH), 256 threads, 1 CTA/SM (202 KB smem).
// ---------------------------------------------------------------------------
__global__ __launch_bounds__(256, 1) void qk_kxt_kernel(
    const float* __restrict__ x,
    const float* __restrict__ bq, const float* __restrict__ bk)
{
    extern __shared__ float sm[];
    const uint32_t smb = sm_u32(sm);
    const int b  = blockIdx.y;
    const int n0 = blockIdx.x * 128;
    const int t  = threadIdx.x;
    const int wid = t >> 5, lane = t & 31;
    const float* xb = x + (size_t)b * CH * NN;

    // warp tile: wm in {0,1} (64 m rows), wn in {0..3} (32 n cols)
    const int wm = wid & 1, wn = wid >> 1;
    const int g  = lane >> 2, tq = lane & 3;

    float acc[4][4][4];
#pragma unroll
    for (int i = 0; i < 4; i++)
#pragma unroll
        for (int j = 0; j < 4; j++)
#pragma unroll
            for (int e = 0; e < 4; e++) acc[i][j][e] = 0.0f;

    // ---- prologue: stage chunk 0 (x float tile + A panels) ----
#pragma unroll
    for (int r = 0; r < 16; r++) {
        int id = t + r * 256;
        int row = id >> 5, f4 = id & 31;
        cpa16(smb + XS_OFF + (uint32_t)(row * 132 + f4 * 4) * 4,
              xb + (size_t)row * NN + n0 + f4 * 4);
    }
#pragma unroll
    for (int r = 0; r < 8; r++) {
        int id = t + r * 256;
        int row = id >> 4, seg = id & 15;
        cpa16(smb + AH_OFF + (uint32_t)(row * 136 + seg * 8) * 2, g_Wh + row * CH + seg * 8);
        cpa16(smb + AL_OFF + (uint32_t)(row * 136 + seg * 8) * 2, g_Wl + row * CH + seg * 8);
    }
    cp_commit();

    const int cn    = t & 127;     // conversion: n index
    const int chalf = t >> 7;      // 0/1
    const int arow  = lane & 15, acol = lane >> 4;

    for (int q = 0; q < 4; q++) {
        cp_wait0();
        __syncthreads();   // staging q + A q ready; all prior MMA done

        // ---- convert staging x[k][n] float -> Bt[n][k] bf16 hi/lo (pitch 136) ----
#pragma unroll
        for (int j = 0; j < 8; j++) {
            const int ko = 2 * j + chalf;          // k-octet 0..15
            float v[8];
#pragma unroll
            for (int e = 0; e < 8; e++)
                v[e] = sm[(ko * 8 + e) * 132 + cn];
            __nv_bfloat162 h[4], l[4];
#pragma unroll
            for (int p = 0; p < 4; p++) {
                h[p] = __floats2bfloat162_rn(v[2 * p], v[2 * p + 1]);
                float h0 = __bfloat162float(__low2bfloat16(h[p]));
                float h1 = __bfloat162float(__high2bfloat16(h[p]));
                l[p] = __floats2bfloat162_rn(v[2 * p] - h0, v[2 * p + 1] - h1);
            }
            uint4 uh = *(uint4*)h;
            uint4 ul = *(uint4*)l;
            *(uint4*)((char*)sm + BH_OFF + cn * 272 + ko * 16) = uh;
            *(uint4*)((char*)sm + BL_OFF + cn * 272 + ko * 16) = ul;
        }
        __syncthreads();

        // ---- prefetch next staging tile (Xs now free) ----
        if (q < 3) {
            const int k0 = (q + 1) * 128;
#pragma unroll
            for (int r = 0; r < 16; r++) {
                int id = t + r * 256;
                int row = id >> 5, f4 = id & 31;
                cpa16(smb + XS_OFF + (uint32_t)(row * 132 + f4 * 4) * 4,
                      xb + (size_t)(k0 + row) * NN + n0 + f4 * 4);
            }
            cp_commit();
        }

        // ---- MMA: 8 k16 steps, 3 split-products ----
#pragma unroll
        for (int kk = 0; kk < 8; kk++) {
            const uint32_t kbyte = (uint32_t)(kk * 16 + acol * 8) * 2;
            uint32_t bh[2][4], bl[2][4];
#pragma unroll
            for (int jj = 0; jj < 2; jj++) {
                const uint32_t baddr = (uint32_t)((wn * 32 + jj * 16 + arow) * 272) + kbyte;
                ldsm4(bh[jj][0], bh[jj][1], bh[jj][2], bh[jj][3], smb + BH_OFF + baddr);
                ldsm4(bl[jj][0], bl[jj][1], bl[jj][2], bl[jj][3], smb + BL_OFF + baddr);
            }
#pragma unroll
            for (int i = 0; i < 4; i++) {
                const uint32_t aaddr = (uint32_t)((wm * 64 + i * 16 + arow) * 272) + kbyte;
                uint32_t ah0, ah1, ah2, ah3, al0, al1, al2, al3;
                ldsm4(ah0, ah1, ah2, ah3, smb + AH_OFF + aaddr);
                ldsm4(al0, al1, al2, al3, smb + AL_OFF + aaddr);
#pragma unroll
                for (int j = 0; j < 4; j++) {
                    const int jj = j >> 1, jo = j & 1;
                    uint32_t bb0 = bh[jj][jo], bb1 = bh[jj][jo + 2];
                    uint32_t bc0 = bl[jj][jo], bc1 = bl[jj][jo + 2];
                    mma16816(acc[i][j], ah0, ah1, ah2, ah3, bb0, bb1);
                    mma16816(acc[i][j], ah0, ah1, ah2, ah3, bc0, bc1);
                    mma16816(acc[i][j], al0, al1, al2, al3, bb0, bb1);
                }
            }
        }

        // ---- A panels for next chunk (A buffers free after all warps pass) ----
        if (q < 3) {
            __syncthreads();
            const int k0 = (q + 1) * 128;
#pragma unroll
            for (int r = 0; r < 8; r++) {
                int id = t + r * 256;
                int row = id >> 4, seg = id & 15;
                cpa16(smb + AH_OFF + (uint32_t)(row * 136 + seg * 8) * 2,
                      g_Wh + row * CH + k0 + seg * 8);
                cpa16(smb + AL_OFF + (uint32_t)(row * 136 + seg * 8) * 2,
                      g_Wl + row * CH + k0 + seg * 8);
            }
            cp_commit();
        }
    }
    __syncthreads();   // all MMA done before Kf_s overwrites the A region

    // ---- epilogue: bias + delu; Q rows (wm=0) -> gmem bf16 hi/lo, K rows -> smem ----
    float* Kf_s = sm + (AH_OFF / 4);   // [64][132]
    {
#pragma unroll
        for (int i = 0; i < 4; i++) {
#pragma unroll
            for (int h = 0; h < 2; h++) {
                const int rl = i * 16 + g + 8 * h;     // row within this wm group (0..63)
                const float bias = (wm == 0) ? bq[rl] : bk[rl];
#pragma unroll
                for (int j = 0; j < 4; j++) {
                    const int col = wn * 32 + j * 8 + 2 * tq;
                    float2 o;
                    o.x = delu(acc[i][j][2 * h] + bias);
                    o.y = delu(acc[i][j][2 * h + 1] + bias);
                    if (wm == 0) {
                        const size_t idx = ((size_t)b * DD + rl) * NN + n0 + col;
                        __nv_bfloat162 hp = __floats2bfloat162_rn(o.x, o.y);
                        float h0 = __bfloat162float(__low2bfloat16(hp));
                        float h1 = __bfloat162float(__high2bfloat16(hp));
                        __nv_bfloat162 lp = __floats2bfloat162_rn(o.x - h0, o.y - h1);
                        *(__nv_bfloat162*)&g_Qh[idx] = hp;
                        *(__nv_bfloat162*)&g_Ql[idx] = lp;
                    } else {
                        *(float2*)&Kf_s[rl * 132 + col] = o;
                    }
                }
            }
        }
    }
    __syncthreads();

    // ---- Ksum partials ----
    {
#pragma unroll
        for (int r = 0; r < 8; r++) {
            const int m = wid * 8 + r;
            float s = Kf_s[m * 132 + lane] + Kf_s[m * 132 + lane + 32]
                    + Kf_s[m * 132 + lane + 64] + Kf_s[m * 132 + lane + 96];
#pragma unroll
            for (int off = 16; off > 0; off >>= 1)
                s += __shfl_down_sync(0xffffffffu, s, off);
            if (lane == 0) atomicAdd(&g_Ksum[b * DD + m], s);
        }
    }

    // ---- phase 2: KXt += Kf_s @ x^T, 4 c-chunks of 128, micro 8m x 4c ----
    const int txc = t & 31, tym = t >> 5;
    for (int c0 = 0; c0 < CH; c0 += 128) {
        __syncthreads();
#pragma unroll
        for (int r = 0; r < 16; r++) {
            const int id = t + r * 256;
            const int c = id >> 5, nf = id & 31;
            *(float4*)&sm[c * 132 + nf * 4] =
                *(const float4*)&xb[(size_t)(c0 + c) * NN + n0 + nf * 4];
        }
        __syncthreads();

        float accP[8][4];
#pragma unroll
        for (int i = 0; i < 8; i++)
#pragma unroll
            for (int j = 0; j < 4; j++) accP[i][j] = 0.0f;

#pragma unroll 4
        for (int n4 = 0; n4 < 128; n4 += 4) {
            float4 X[4];
#pragma unroll
            for (int j = 0; j < 4; j++)
                X[j] = *(const float4*)&sm[(txc + 32 * j) * 132 + n4];
#pragma unroll
            for (int i = 0; i < 8; i++) {
                float4 K4 = *(const float4*)&Kf_s[(tym * 8 + i) * 132 + n4];
#pragma unroll
                for (int j = 0; j < 4; j++) {
                    accP[i][j] += K4.x * X[j].x;
                    accP[i][j] += K4.y * X[j].y;
                    accP[i][j] += K4.z * X[j].z;
                    accP[i][j] += K4.w * X[j].w;
                }
            }
        }
#pragma unroll
        for (int i = 0; i < 8; i++) {
            const int m = tym * 8 + i;
#pragma unroll
            for (int j = 0; j < 4; j++)
                atomicAdd(&g_KXt[((size_t)b * DD + m) * CH + c0 + txc + 32 * j], accP[i][j]);
        }
    }
}

// ---------------------------------------------------------------------------
// 2) KV = KXt_flat[512,512] @ wv^T + (Ksum-EPS)*bv.  K split into 16 chunks.
// ---------------------------------------------------------------------------
__global__ __launch_bounds__(256) void kv_kernel(
    const float* __restrict__ wv, const float* __restrict__ bv)
{
    __shared__ float As[32][65];
    __shared__ float Bs[32][129];
    const int e0 = blockIdx.x * 128;
    const int m0 = blockIdx.y * 64;
    const int c0 = blockIdx.z * 32;
    const int t  = threadIdx.x;
    const int tx = t & 31, ty = t >> 5;

    float acc[8][4];
#pragma unroll
    for (int i = 0; i < 8; i++)
#pragma unroll
        for (int j = 0; j < 4; j++) acc[i][j] = 0.0f;

    {
        const int k0 = c0;
#pragma unroll
        for (int r = 0; r < 8; r++) {
            int idx = t + r * 256;
            int m = idx >> 5, kk = idx & 31;
            As[kk][m] = g_KXt[(size_t)(m0 + m) * CH + k0 + kk];
        }
#pragma unroll
        for (int r = 0; r < 16; r++) {
            int idx = t + r * 256;
            int e = idx >> 5, kk = idx & 31;
            Bs[kk][e] = wv[(size_t)(e0 + e) * CH + k0 + kk];
        }
        __syncthreads();
#pragma unroll
        for (int kk = 0; kk < 32; kk++) {
            float a[8], bb[4];
#pragma unroll
            for (int i = 0; i < 8; i++) a[i] = As[kk][ty * 8 + i];
#pragma unroll
            for (int j = 0; j < 4; j++) bb[j] = Bs[kk][tx * 4 + j];
#pragma unroll
            for (int i = 0; i < 8; i++)
#pragma unroll
                for (int j = 0; j < 4; j++) acc[i][j] += a[i] * bb[j];
        }
    }

#pragma unroll
    for (int i = 0; i < 8; i++) {
        int m = m0 + ty * 8 + i;
#pragma unroll
        for (int j = 0; j < 4; j++) {
            int e = e0 + tx * 4 + j;
            float v = acc[i][j];
            if (blockIdx.z == 0) v += (g_Ksum[m] - EPSF) * bv[e];
            atomicAdd(&g_KV[(size_t)m * CH + e], v);
        }
    }
}

// ---------------------------------------------------------------------------
// 3) out = x + gamma * norm[n] * (KV^T @ Qf).  bf16-split mma, c128 x n128, K=64.
//    grid = (NN/128, CH/128, BATCH), 256 threads, 2 CTA/SM.
// ---------------------------------------------------------------------------
__global__ __launch_bounds__(256, 2) void out_kernel(
    const float* __restrict__ x, const float* __restrict__ gamma,
    float* __restrict__ out)
{
    extern __shared__ char smc[];
    const uint32_t smb = sm_u32(smc);
    __nv_bfloat16* QH = (__nv_bfloat16*)(smc + O_QH);   // [64 d][136 n]
    __nv_bfloat16* QL = (__nv_bfloat16*)(smc + O_QL);
    __nv_bfloat16* AH = (__nv_bfloat16*)(smc + O_AH);   // [128 c][72 d]
    __nv_bfloat16* AL = (__nv_bfloat16*)(smc + O_AL);
    float* Ks = (float*)(smc + O_KS);
    float* NV = (float*)(smc + O_NV);

    const int b  = blockIdx.z;
    const int c0 = blockIdx.y * 128;
    const int n0 = blockIdx.x * 128;
    const int t  = threadIdx.x;
    const int wid = t >> 5, lane = t & 31;
    const float* kv = g_KV + (size_t)b * DD * CH;

    // ---- load Q planes via cp.async (row-major d x n, pitch 136 halves) ----
#pragma unroll
    for (int r = 0; r < 4; r++) {
        const int id = t + r * 256;
        const int row = id >> 4, ch = id & 15;
        const size_t src = ((size_t)b * DD + row) * NN + n0 + ch * 8;
        cpa16(smb + O_QH + (uint32_t)(row * 136 + ch * 8) * 2, g_Qh + src);
        cpa16(smb + O_QL + (uint32_t)(row * 136 + ch * 8) * 2, g_Ql + src);
    }
    cp_commit();

    if (t < 64) Ks[t] = g_Ksum[b * DD + t];

    // ---- KV fp32 -> bf16 hi/lo, transposed to [c][d] ----
#pragma unroll
    for (int r = 0; r < 8; r++) {
        const int id = t + r * 256;
        const int d = id >> 5, cf = id & 31;
        float4 v = *(const float4*)&kv[(size_t)d * CH + c0 + cf * 4];
        float vv[4] = {v.x, v.y, v.z, v.w};
#pragma unroll
        for (int e = 0; e < 4; e++) {
            const int c = cf * 4 + e;
            __nv_bfloat16 h = __float2bfloat16_rn(vv[e]);
            AH[c * 72 + d] = h;
            AL[c * 72 + d] = __float2bfloat16_rn(vv[e] - __bfloat162float(h));
        }
    }
    cp_wait0();
    __syncthreads();

    // ---- norm vector ----
    if (t < 128) {
        float s = 0.0f;
#pragma unroll
        for (int d = 0; d < 64; d++)
            s += (__bfloat162float(QH[d * 136 + t]) + __bfloat162float(QL[d * 136 + t])) * Ks[d];
        NV[t] = 1.0f / s;
    }
    __syncthreads();

    // ---- mma: warp tile 64c x 32n; wc = wid&1, wn = wid>>1 ----
    const int wc = wid & 1, wn = wid >> 1;
    const int arow = lane & 15, acol = lane >> 4;

    float acc[4][4][4];
#pragma unroll
    for (int i = 0; i < 4; i++)
#pragma unroll
        for (int j = 0; j < 4; j++)
#pragma unroll
            for (int e = 0; e < 4; e++) acc[i][j][e] = 0.0f;

#pragma unroll
    for (int kk = 0; kk < 4; kk++) {
        // B frags from row-major [d][n] via ldmatrix.trans
        uint32_t bh[2][4], bl[2][4];
#pragma unroll
        for (int j16 = 0; j16 < 2; j16++) {
            const uint32_t boff =
                (uint32_t)((kk * 16 + arow) * 136 + wn * 32 + j16 * 16 + acol * 8) * 2;
            ldsm4t(bh[j16][0], bh[j16][1], bh[j16][2], bh[j16][3], smb + O_QH + boff);
            ldsm4t(bl[j16][0], bl[j16][1], bl[j16][2], bl[j16][3], smb + O_QL + boff);
        }
#pragma unroll
        for (int i = 0; i < 4; i++) {
            const uint32_t aoff =
                (uint32_t)((wc * 64 + i * 16 + arow) * 72 + kk * 16 + acol * 8) * 2;
            uint32_t ah0, ah1, ah2, ah3, al0, al1, al2, al3;
            ldsm4(ah0, ah1, ah2, ah3, smb + O_AH + aoff);
            ldsm4(al0, al1, al2, al3, smb + O_AL + aoff);
#pragma unroll
            for (int j = 0; j < 4; j++) {
                const int jj = j >> 1, jo = j & 1;
                // trans frag order: r0=(k lo,n lo) r1=(k hi,n lo) r2=(k lo,n hi) r3=(k hi,n hi)
                uint32_t bb0 = bh[jj][2 * jo], bb1 = bh[jj][2 * jo + 1];
                uint32_t bc0 = bl[jj][2 * jo], bc1 = bl[jj][2 * jo + 1];
                mma16816(acc[i][j], ah0, ah1, ah2, ah3, bb0, bb1);
                mma16816(acc[i][j], ah0, ah1, ah2, ah3, bc0, bc1);
                mma16816(acc[i][j], al0, al1, al2, al3, bb0, bb1);
            }
        }
    }

    // ---- epilogue: out = x + g * norm * acc ----
    const float gma = gamma[0];
    const int gg = lane >> 2, tq = lane & 3;
#pragma unroll
    for (int i = 0; i < 4; i++) {
#pragma unroll
        for (int h = 0; h < 2; h++) {
            const int cc = c0 + wc * 64 + i * 16 + gg + 8 * h;
            const size_t base = ((size_t)b * CH + cc) * NN + n0;
#pragma unroll
            for (int j = 0; j < 4; j++) {
                const int col = wn * 32 + j * 8 + 2 * tq;
                float2 xv = *(const float2*)&x[base + col];
                float2 o;
                o.x = xv.x + gma * NV[col]     * acc[i][j][2 * h];
                o.y = xv.y + gma * NV[col + 1] * acc[i][j][2 * h + 1];
                *(float2*)&out[base + col] = o;
            }
        }
    }
}

// ---------------------------------------------------------------------------
extern "C" void kernel_launch(void* const* d_in, const int* in_sizes, int n_in,
                              void* d_out, int out_size)
{
    const float* x     = (const float*)d_in[0];
    const float* wq    = (const float*)d_in[1];
    const float* bq    = (const float*)d_in[2];
    const float* wk    = (const float*)d_in[3];
    const float* bk    = (const float*)d_in[4];
    const float* wv    = (const float*)d_in[5];
    const float* bv    = (const float*)d_in[6];
    const float* gamma = (const float*)d_in[7];
    float* out = (float*)d_out;

    static bool attr_done = false;
    if (!attr_done) {
        cudaFuncSetAttribute(qk_kxt_kernel, cudaFuncAttributeMaxDynamicSharedMemorySize,
                             SMEM_TOT);
        cudaFuncSetAttribute(out_kernel, cudaFuncAttributeMaxDynamicSharedMemorySize,
                             O_SMEM);
        attr_done = true;
    }

    init_kernel<<<(BATCH * DD * CH + 255) / 256, 256>>>(wq, wk);
    qk_kxt_kernel<<<dim3(NN / 128, BATCH), 256, SMEM_TOT>>>(x, bq, bk);
    kv_kernel<<<dim3(CH / 128, (BATCH * DD) / 64, 16), 256>>>(wv, bv);
    out_kernel<<<dim3(NN / 128, CH / 128, BATCH), 256, O_SMEM>>>(x, gamma, out);
}

// round 14
// speedup vs baseline: 1.0798x; 1.0798x over previous
#include <cuda_runtime.h>
#include <cuda_bf16.h>
#include <cstdint>

#define BATCH 8
#define CH    512
#define DD    64
#define NN    4096
#define EPSF  1e-10f

typedef unsigned long long ull;

// ---------------- scratch (__device__ globals; no allocs allowed) ----------
__device__ __align__(16) __nv_bfloat16 g_Wh[128 * CH];   // stacked wq/wk hi, [m][k] row-major
__device__ __align__(16) __nv_bfloat16 g_Wl[128 * CH];   // lo residual
__device__ __align__(16) __nv_bfloat16 g_Qh[BATCH * DD * NN];  // delu(Q) hi, [b][d][n]
__device__ __align__(16) __nv_bfloat16 g_Ql[BATCH * DD * NN];  // delu(Q) lo residual
__device__ __align__(16) __nv_bfloat16 g_KVth[BATCH * CH * DD]; // KV hi, transposed [b][c][d]
__device__ __align__(16) __nv_bfloat16 g_KVtl[BATCH * CH * DD]; // KV lo residual
__device__ float g_KXt[BATCH * DD * CH];   // Kf @ x^T (atomic accum)
__device__ float g_KV[BATCH * DD * CH];    // KXt @ wv^T + bias (atomic accum)
__device__ float g_Ksum[BATCH * DD];       // EPS + sum_n Kf
__device__ float g_norm[BATCH * NN];       // 1 / (Qf . Ksum)

__device__ __forceinline__ float delu(float v) {
    return 10.0f * fmaxf(v, 0.0f) + __expf(10.0f * fminf(v, 0.0f));
}

// ---------------- cp.async ----------
__device__ __forceinline__ void cpa16(uint32_t dst, const void* src) {
    asm volatile("cp.async.cg.shared.global [%0], [%1], 16;" :: "r"(dst), "l"(src));
}
__device__ __forceinline__ void cp_commit() { asm volatile("cp.async.commit_group;" ::: "memory"); }
__device__ __forceinline__ void cp_wait0()  { asm volatile("cp.async.wait_group 0;" ::: "memory"); }
__device__ __forceinline__ uint32_t sm_u32(const void* p) {
    return (uint32_t)__cvta_generic_to_shared(p);
}

// ---------------- mma.sync bf16 helpers ----------
__device__ __forceinline__ void ldsm4(uint32_t& r0, uint32_t& r1, uint32_t& r2, uint32_t& r3,
                                      uint32_t addr) {
    asm volatile("ldmatrix.sync.aligned.m8n8.x4.shared.b16 {%0,%1,%2,%3}, [%4];"
                 : "=r"(r0), "=r"(r1), "=r"(r2), "=r"(r3) : "r"(addr));
}
__device__ __forceinline__ void ldsm4t(uint32_t& r0, uint32_t& r1, uint32_t& r2, uint32_t& r3,
                                       uint32_t addr) {
    asm volatile("ldmatrix.sync.aligned.m8n8.x4.trans.shared.b16 {%0,%1,%2,%3}, [%4];"
                 : "=r"(r0), "=r"(r1), "=r"(r2), "=r"(r3) : "r"(addr));
}
__device__ __forceinline__ void mma16816(float* c, uint32_t a0, uint32_t a1, uint32_t a2,
                                         uint32_t a3, uint32_t b0, uint32_t b1) {
    asm volatile("mma.sync.aligned.m16n8k16.row.col.f32.bf16.bf16.f32 "
                 "{%0,%1,%2,%3},{%4,%5,%6,%7},{%8,%9},{%0,%1,%2,%3};"
                 : "+f"(c[0]), "+f"(c[1]), "+f"(c[2]), "+f"(c[3])
                 : "r"(a0), "r"(a1), "r"(a2), "r"(a3), "r"(b0), "r"(b1));
}

// smem byte offsets (qk_kxt kernel). Pitch 136 halves (272 B) for mma tiles.
#define XS_OFF   0         // staging x [128k][132n] float = 67584 B ; phase2 Xs; Kf_s region below
#define AH_OFF   67584     // Ah [128m][136k] bf16 = 34816 B   (Kf_s [64][132] floats reuses this)
#define AL_OFF   102400
#define BH_OFF   137216    // Bh [128n][136k] bf16
#define BL_OFF   172032
#define SMEM_TOT 206848

// out_kernel smem byte offsets
#define O_QH   0           // [64 d][136 n] bf16 = 17408 B
#define O_QL   17408
#define O_AH   34816       // [128 c][72 d] bf16 = 18432 B
#define O_AL   53248
#define O_NV   71680       // [128] float
#define O_SMEM 72192

// ---------------------------------------------------------------------------
// 0) init: zero accumulators, Ksum = EPS, split W into bf16 hi/lo panels
// ---------------------------------------------------------------------------
__global__ void init_kernel(const float* __restrict__ wq, const float* __restrict__ wk) {
    int i = blockIdx.x * blockDim.x + threadIdx.x;
    if (i < BATCH * DD * CH) { g_KXt[i] = 0.0f; g_KV[i] = 0.0f; }
    if (i < BATCH * DD) g_Ksum[i] = EPSF;
    if (i < 128 * CH) {
        int m = i >> 9, k = i & 511;
        float w = (m < 64) ? wq[(size_t)m * CH + k] : wk[(size_t)(m - 64) * CH + k];
        __nv_bfloat16 h = __float2bfloat16_rn(w);
        __nv_bfloat16 l = __float2bfloat16_rn(w - __bfloat162float(h));
        g_Wh[i] = h;
        g_Wl[i] = l;
    }
}

// ---------------------------------------------------------------------------
// 1) FUSED: Q/K projection via mma.sync bf16-split + delu + Ksum + KXt (FFMA).
//    grid = (NN/128, BATCH), 256 threads, 1 CTA/SM (202 KB smem).
// ---------------------------------------------------------------------------
__global__ __launch_bounds__(256, 1) void qk_kxt_kernel(
    const float* __restrict__ x,
    const float* __restrict__ bq, const float* __restrict__ bk)
{
    extern __shared__ float sm[];
    const uint32_t smb = sm_u32(sm);
    const int b  = blockIdx.y;
    const int n0 = blockIdx.x * 128;
    const int t  = threadIdx.x;
    const int wid = t >> 5, lane = t & 31;
    const float* xb = x + (size_t)b * CH * NN;

    // warp tile: wm in {0,1} (64 m rows), wn in {0..3} (32 n cols)
    const int wm = wid & 1, wn = wid >> 1;
    const int g  = lane >> 2, tq = lane & 3;

    float acc[4][4][4];
#pragma unroll
    for (int i = 0; i < 4; i++)
#pragma unroll
        for (int j = 0; j < 4; j++)
#pragma unroll
            for (int e = 0; e < 4; e++) acc[i][j][e] = 0.0f;

    // ---- prologue: stage chunk 0 (x float tile + A panels) ----
#pragma unroll
    for (int r = 0; r < 16; r++) {
        int id = t + r * 256;
        int row = id >> 5, f4 = id & 31;
        cpa16(smb + XS_OFF + (uint32_t)(row * 132 + f4 * 4) * 4,
              xb + (size_t)row * NN + n0 + f4 * 4);
    }
#pragma unroll
    for (int r = 0; r < 8; r++) {
        int id = t + r * 256;
        int row = id >> 4, seg = id & 15;
        cpa16(smb + AH_OFF + (uint32_t)(row * 136 + seg * 8) * 2, g_Wh + row * CH + seg * 8);
        cpa16(smb + AL_OFF + (uint32_t)(row * 136 + seg * 8) * 2, g_Wl + row * CH + seg * 8);
    }
    cp_commit();

    const int cn    = t & 127;     // conversion: n index
    const int chalf = t >> 7;      // 0/1
    const int arow  = lane & 15, acol = lane >> 4;

    for (int q = 0; q < 4; q++) {
        cp_wait0();
        __syncthreads();   // staging q + A q ready; all prior MMA done

        // ---- convert staging x[k][n] float -> Bt[n][k] bf16 hi/lo (pitch 136) ----
#pragma unroll
        for (int j = 0; j < 8; j++) {
            const int ko = 2 * j + chalf;          // k-octet 0..15
            float v[8];
#pragma unroll
            for (int e = 0; e < 8; e++)
                v[e] = sm[(ko * 8 + e) * 132 + cn];
            __align__(16) __nv_bfloat162 h[4];
            __align__(16) __nv_bfloat162 l[4];
#pragma unroll
            for (int p = 0; p < 4; p++) {
                h[p] = __floats2bfloat162_rn(v[2 * p], v[2 * p + 1]);
                float h0 = __bfloat162float(__low2bfloat16(h[p]));
                float h1 = __bfloat162float(__high2bfloat16(h[p]));
                l[p] = __floats2bfloat162_rn(v[2 * p] - h0, v[2 * p + 1] - h1);
            }
            uint4 uh = *(uint4*)h;
            uint4 ul = *(uint4*)l;
            *(uint4*)((char*)sm + BH_OFF + cn * 272 + ko * 16) = uh;
            *(uint4*)((char*)sm + BL_OFF + cn * 272 + ko * 16) = ul;
        }
        __syncthreads();

        // ---- prefetch next staging tile (Xs now free) ----
        if (q < 3) {
            const int k0 = (q + 1) * 128;
#pragma unroll
            for (int r = 0; r < 16; r++) {
                int id = t + r * 256;
                int row = id >> 5, f4 = id & 31;
                cpa16(smb + XS_OFF + (uint32_t)(row * 132 + f4 * 4) * 4,
                      xb + (size_t)(k0 + row) * NN + n0 + f4 * 4);
            }
            cp_commit();
        }

        // ---- MMA: 8 k16 steps, 3 split-products ----
#pragma unroll
        for (int kk = 0; kk < 8; kk++) {
            const uint32_t kbyte = (uint32_t)(kk * 16 + acol * 8) * 2;
            uint32_t bh[2][4], bl[2][4];
#pragma unroll
            for (int jj = 0; jj < 2; jj++) {
                const uint32_t baddr = (uint32_t)((wn * 32 + jj * 16 + arow) * 272) + kbyte;
                ldsm4(bh[jj][0], bh[jj][1], bh[jj][2], bh[jj][3], smb + BH_OFF + baddr);
                ldsm4(bl[jj][0], bl[jj][1], bl[jj][2], bl[jj][3], smb + BL_OFF + baddr);
            }
#pragma unroll
            for (int i = 0; i < 4; i++) {
                const uint32_t aaddr = (uint32_t)((wm * 64 + i * 16 + arow) * 272) + kbyte;
                uint32_t ah0, ah1, ah2, ah3, al0, al1, al2, al3;
                ldsm4(ah0, ah1, ah2, ah3, smb + AH_OFF + aaddr);
                ldsm4(al0, al1, al2, al3, smb + AL_OFF + aaddr);
#pragma unroll
                for (int j = 0; j < 4; j++) {
                    const int jj = j >> 1, jo = j & 1;
                    uint32_t bb0 = bh[jj][jo], bb1 = bh[jj][jo + 2];
                    uint32_t bc0 = bl[jj][jo], bc1 = bl[jj][jo + 2];
                    mma16816(acc[i][j], ah0, ah1, ah2, ah3, bb0, bb1);
                    mma16816(acc[i][j], ah0, ah1, ah2, ah3, bc0, bc1);
                    mma16816(acc[i][j], al0, al1, al2, al3, bb0, bb1);
                }
            }
        }

        // ---- A panels for next chunk (A buffers free after all warps pass) ----
        if (q < 3) {
            __syncthreads();
            const int k0 = (q + 1) * 128;
#pragma unroll
            for (int r = 0; r < 8; r++) {
                int id = t + r * 256;
                int row = id >> 4, seg = id & 15;
                cpa16(smb + AH_OFF + (uint32_t)(row * 136 + seg * 8) * 2,
                      g_Wh + row * CH + k0 + seg * 8);
                cpa16(smb + AL_OFF + (uint32_t)(row * 136 + seg * 8) * 2,
                      g_Wl + row * CH + k0 + seg * 8);
            }
            cp_commit();
        }
    }
    __syncthreads();   // all MMA done before Kf_s overwrites the A region

    // ---- epilogue: bias + delu; Q rows (wm=0) -> gmem bf16 hi/lo, K rows -> smem ----
    float* Kf_s = sm + (AH_OFF / 4);   // [64][132]
    {
#pragma unroll
        for (int i = 0; i < 4; i++) {
#pragma unroll
            for (int h = 0; h < 2; h++) {
                const int rl = i * 16 + g + 8 * h;     // row within this wm group (0..63)
                const float bias = (wm == 0) ? bq[rl] : bk[rl];
#pragma unroll
                for (int j = 0; j < 4; j++) {
                    const int col = wn * 32 + j * 8 + 2 * tq;
                    float2 o;
                    o.x = delu(acc[i][j][2 * h] + bias);
                    o.y = delu(acc[i][j][2 * h + 1] + bias);
                    if (wm == 0) {
                        const size_t idx = ((size_t)b * DD + rl) * NN + n0 + col;
                        __nv_bfloat162 hp = __floats2bfloat162_rn(o.x, o.y);
                        float h0 = __bfloat162float(__low2bfloat16(hp));
                        float h1 = __bfloat162float(__high2bfloat16(hp));
                        __nv_bfloat162 lp = __floats2bfloat162_rn(o.x - h0, o.y - h1);
                        *(__nv_bfloat162*)&g_Qh[idx] = hp;
                        *(__nv_bfloat162*)&g_Ql[idx] = lp;
                    } else {
                        *(float2*)&Kf_s[rl * 132 + col] = o;
                    }
                }
            }
        }
    }
    __syncthreads();

    // ---- Ksum partials ----
    {
#pragma unroll
        for (int r = 0; r < 8; r++) {
            const int m = wid * 8 + r;
            float s = Kf_s[m * 132 + lane] + Kf_s[m * 132 + lane + 32]
                    + Kf_s[m * 132 + lane + 64] + Kf_s[m * 132 + lane + 96];
#pragma unroll
            for (int off = 16; off > 0; off >>= 1)
                s += __shfl_down_sync(0xffffffffu, s, off);
            if (lane == 0) atomicAdd(&g_Ksum[b * DD + m], s);
        }
    }

    // ---- phase 2: KXt += Kf_s @ x^T, 4 c-chunks of 128, micro 8m x 4c ----
    const int txc = t & 31, tym = t >> 5;
    for (int c0 = 0; c0 < CH; c0 += 128) {
        __syncthreads();
#pragma unroll
        for (int r = 0; r < 16; r++) {
            const int id = t + r * 256;
            const int c = id >> 5, nf = id & 31;
            *(float4*)&sm[c * 132 + nf * 4] =
                *(const float4*)&xb[(size_t)(c0 + c) * NN + n0 + nf * 4];
        }
        __syncthreads();

        float accP[8][4];
#pragma unroll
        for (int i = 0; i < 8; i++)
#pragma unroll
            for (int j = 0; j < 4; j++) accP[i][j] = 0.0f;

#pragma unroll 4
        for (int n4 = 0; n4 < 128; n4 += 4) {
            float4 X[4];
#pragma unroll
            for (int j = 0; j < 4; j++)
                X[j] = *(const float4*)&sm[(txc + 32 * j) * 132 + n4];
#pragma unroll
            for (int i = 0; i < 8; i++) {
                float4 K4 = *(const float4*)&Kf_s[(tym * 8 + i) * 132 + n4];
#pragma unroll
                for (int j = 0; j < 4; j++) {
                    accP[i][j] += K4.x * X[j].x;
                    accP[i][j] += K4.y * X[j].y;
                    accP[i][j] += K4.z * X[j].z;
                    accP[i][j] += K4.w * X[j].w;
                }
            }
        }
#pragma unroll
        for (int i = 0; i < 8; i++) {
            const int m = tym * 8 + i;
#pragma unroll
            for (int j = 0; j < 4; j++)
                atomicAdd(&g_KXt[((size_t)b * DD + m) * CH + c0 + txc + 32 * j], accP[i][j]);
        }
    }
}

// ---------------------------------------------------------------------------
// 1b) norm: g_norm[b][n] = 1 / sum_d (Qh+Ql)[b][d][n] * Ksum[b][d]
//     grid = (NN/256, BATCH), 256 threads.
// ---------------------------------------------------------------------------
__global__ __launch_bounds__(256) void norm_kernel() {
    __shared__ float Ks[DD];
    const int b = blockIdx.y;
    const int n = blockIdx.x * 256 + threadIdx.x;
    if (threadIdx.x < DD) Ks[threadIdx.x] = g_Ksum[b * DD + threadIdx.x];
    __syncthreads();
    float s = 0.0f;
#pragma unroll 8
    for (int d = 0; d < DD; d++) {
        const size_t idx = ((size_t)b * DD + d) * NN + n;
        s += (__bfloat162float(g_Qh[idx]) + __bfloat162float(g_Ql[idx])) * Ks[d];
    }
    g_norm[(size_t)b * NN + n] = 1.0f / s;
}

// ---------------------------------------------------------------------------
// 2) KV = KXt_flat[512,512] @ wv^T + (Ksum-EPS)*bv.  K split into 16 chunks.
// ---------------------------------------------------------------------------
__global__ __launch_bounds__(256) void kv_kernel(
    const float* __restrict__ wv, const float* __restrict__ bv)
{
    __shared__ float As[32][65];
    __shared__ float Bs[32][129];
    const int e0 = blockIdx.x * 128;
    const int m0 = blockIdx.y * 64;
    const int c0 = blockIdx.z * 32;
    const int t  = threadIdx.x;
    const int tx = t & 31, ty = t >> 5;

    float acc[8][4];
#pragma unroll
    for (int i = 0; i < 8; i++)
#pragma unroll
        for (int j = 0; j < 4; j++) acc[i][j] = 0.0f;

    {
        const int k0 = c0;
#pragma unroll
        for (int r = 0; r < 8; r++) {
            int idx = t + r * 256;
            int m = idx >> 5, kk = idx & 31;
            As[kk][m] = g_KXt[(size_t)(m0 + m) * CH + k0 + kk];
        }
#pragma unroll
        for (int r = 0; r < 16; r++) {
            int idx = t + r * 256;
            int e = idx >> 5, kk = idx & 31;
            Bs[kk][e] = wv[(size_t)(e0 + e) * CH + k0 + kk];
        }
        __syncthreads();
#pragma unroll
        for (int kk = 0; kk < 32; kk++) {
            float a[8], bb[4];
#pragma unroll
            for (int i = 0; i < 8; i++) a[i] = As[kk][ty * 8 + i];
#pragma unroll
            for (int j = 0; j < 4; j++) bb[j] = Bs[kk][tx * 4 + j];
#pragma unroll
            for (int i = 0; i < 8; i++)
#pragma unroll
                for (int j = 0; j < 4; j++) acc[i][j] += a[i] * bb[j];
        }
    }

#pragma unroll
    for (int i = 0; i < 8; i++) {
        int m = m0 + ty * 8 + i;
#pragma unroll
        for (int j = 0; j < 4; j++) {
            int e = e0 + tx * 4 + j;
            float v = acc[i][j];
            if (blockIdx.z == 0) v += (g_Ksum[m] - EPSF) * bv[e];
            atomicAdd(&g_KV[(size_t)m * CH + e], v);
        }
    }
}

// ---------------------------------------------------------------------------
// 2b) kvt: transpose+split g_KV[b][d][c] fp32 -> g_KVth/g_KVtl[b][c][d] bf16.
//     grid = (CH/128, BATCH), 256 threads. Tiny (8 MB total traffic).
//     NOTE: tile pitch 133 floats (532 B) is NOT 16B-aligned per row -> the
//     gmem float4 is loaded into registers and stored with scalar STS.
// ---------------------------------------------------------------------------
__global__ __launch_bounds__(256) void kvt_kernel() {
    __shared__ float tile[DD * 133];   // [d][c_local], pitch 133 (odd, bank-spread)
    const int b  = blockIdx.y;
    const int c0 = blockIdx.x * 128;
    const int t  = threadIdx.x;

#pragma unroll
    for (int r = 0; r < 8; r++) {
        const int id = t + r * 256;
        const int d = id >> 5, cf = id & 31;
        float4 v = *(const float4*)&g_KV[((size_t)b * DD + d) * CH + c0 + cf * 4];
        float* dst = &tile[d * 133 + cf * 4];
        dst[0] = v.x; dst[1] = v.y; dst[2] = v.z; dst[3] = v.w;   // scalar STS (pitch not 16B-aligned)
    }
    __syncthreads();

    // each unit: (c_local, d-octet) -> 8 bf16 hi + 8 bf16 lo (16 B stores)
#pragma unroll
    for (int r = 0; r < 4; r++) {
        const int id = t + r * 256;
        const int cl = id >> 3, dg = (id & 7) * 8;
        __align__(16) __nv_bfloat162 hp[4];
        __align__(16) __nv_bfloat162 lp[4];
#pragma unroll
        for (int p = 0; p < 4; p++) {
            float v0 = tile[(dg + 2 * p) * 133 + cl];
            float v1 = tile[(dg + 2 * p + 1) * 133 + cl];
            hp[p] = __floats2bfloat162_rn(v0, v1);
            float h0 = __bfloat162float(__low2bfloat16(hp[p]));
            float h1 = __bfloat162float(__high2bfloat16(hp[p]));
            lp[p] = __floats2bfloat162_rn(v0 - h0, v1 - h1);
        }
        const size_t idx = ((size_t)b * CH + c0 + cl) * DD + dg;
        *(uint4*)&g_KVth[idx] = *(uint4*)hp;
        *(uint4*)&g_KVtl[idx] = *(uint4*)lp;
    }
}

// ---------------------------------------------------------------------------
// 3) out = x + gamma * norm[n] * (KV^T @ Qf).  bf16-split mma, c128 x n128, K=64.
//    All operands pre-converted; pure load->mma->store.
//    grid = (NN/128, CH/128, BATCH), 256 threads, 2 CTA/SM.
// ---------------------------------------------------------------------------
__global__ __launch_bounds__(256, 2) void out_kernel(
    const float* __restrict__ x, const float* __restrict__ gamma,
    float* __restrict__ out)
{
    extern __shared__ char smc[];
    const uint32_t smb = sm_u32(smc);
    float* NV = (float*)(smc + O_NV);

    const int b  = blockIdx.z;
    const int c0 = blockIdx.y * 128;
    const int n0 = blockIdx.x * 128;
    const int t  = threadIdx.x;
    const int wid = t >> 5, lane = t & 31;

    // ---- cp.async all four bf16 planes ----
#pragma unroll
    for (int r = 0; r < 4; r++) {         // Q planes: [64 d][136 n]
        const int id = t + r * 256;
        const int row = id >> 4, ch = id & 15;
        const size_t src = ((size_t)b * DD + row) * NN + n0 + ch * 8;
        cpa16(smb + O_QH + (uint32_t)(row * 136 + ch * 8) * 2, g_Qh + src);
        cpa16(smb + O_QL + (uint32_t)(row * 136 + ch * 8) * 2, g_Ql + src);
    }
#pragma unroll
    for (int r = 0; r < 4; r++) {         // A planes: [128 c][72 d]
        const int id = t + r * 256;
        const int row = id >> 3, seg = id & 7;
        const size_t src = ((size_t)b * CH + c0 + row) * DD + seg * 8;
        cpa16(smb + O_AH + (uint32_t)(row * 72 + seg * 8) * 2, g_KVth + src);
        cpa16(smb + O_AL + (uint32_t)(row * 72 + seg * 8) * 2, g_KVtl + src);
    }
    cp_commit();
    if (t < 128) NV[t] = g_norm[(size_t)b * NN + n0 + t];
    cp_wait0();
    __syncthreads();

    // ---- mma: warp tile 64c x 32n; wc = wid&1, wn = wid>>1 ----
    const int wc = wid & 1, wn = wid >> 1;
    const int arow = lane & 15, acol = lane >> 4;

    float acc[4][4][4];
#pragma unroll
    for (int i = 0; i < 4; i++)
#pragma unroll
        for (int j = 0; j < 4; j++)
#pragma unroll
            for (int e = 0; e < 4; e++) acc[i][j][e] = 0.0f;

#pragma unroll
    for (int kk = 0; kk < 4; kk++) {
        // B frags from row-major [d][n] via ldmatrix.trans
        uint32_t bh[2][4], bl[2][4];
#pragma unroll
        for (int j16 = 0; j16 < 2; j16++) {
            const uint32_t boff =
                (uint32_t)((kk * 16 + arow) * 136 + wn * 32 + j16 * 16 + acol * 8) * 2;
            ldsm4t(bh[j16][0], bh[j16][1], bh[j16][2], bh[j16][3], smb + O_QH + boff);
            ldsm4t(bl[j16][0], bl[j16][1], bl[j16][2], bl[j16][3], smb + O_QL + boff);
        }
#pragma unroll
        for (int i = 0; i < 4; i++) {
            const uint32_t aoff =
                (uint32_t)((wc * 64 + i * 16 + arow) * 72 + kk * 16 + acol * 8) * 2;
            uint32_t ah0, ah1, ah2, ah3, al0, al1, al2, al3;
            ldsm4(ah0, ah1, ah2, ah3, smb + O_AH + aoff);
            ldsm4(al0, al1, al2, al3, smb + O_AL + aoff);
#pragma unroll
            for (int j = 0; j < 4; j++) {
                const int jj = j >> 1, jo = j & 1;
                // trans frag order: r0=(k lo,n lo) r1=(k hi,n lo) r2=(k lo,n hi) r3=(k hi,n hi)
                uint32_t bb0 = bh[jj][2 * jo], bb1 = bh[jj][2 * jo + 1];
                uint32_t bc0 = bl[jj][2 * jo], bc1 = bl[jj][2 * jo + 1];
                mma16816(acc[i][j], ah0, ah1, ah2, ah3, bb0, bb1);
                mma16816(acc[i][j], ah0, ah1, ah2, ah3, bc0, bc1);
                mma16816(acc[i][j], al0, al1, al2, al3, bb0, bb1);
            }
        }
    }

    // ---- epilogue: out = x + g * norm * acc ----
    const float gma = gamma[0];
    const int gg = lane >> 2, tq = lane & 3;
#pragma unroll
    for (int i = 0; i < 4; i++) {
#pragma unroll
        for (int h = 0; h < 2; h++) {
            const int cc = c0 + wc * 64 + i * 16 + gg + 8 * h;
            const size_t base = ((size_t)b * CH + cc) * NN + n0;
#pragma unroll
            for (int j = 0; j < 4; j++) {
                const int col = wn * 32 + j * 8 + 2 * tq;
                float2 xv = *(const float2*)&x[base + col];
                float2 o;
                o.x = xv.x + gma * NV[col]     * acc[i][j][2 * h];
                o.y = xv.y + gma * NV[col + 1] * acc[i][j][2 * h + 1];
                *(float2*)&out[base + col] = o;
            }
        }
    }
}

// ---------------------------------------------------------------------------
extern "C" void kernel_launch(void* const* d_in, const int* in_sizes, int n_in,
                              void* d_out, int out_size)
{
    const float* x     = (const float*)d_in[0];
    const float* wq    = (const float*)d_in[1];
    const float* bq    = (const float*)d_in[2];
    const float* wk    = (const float*)d_in[3];
    const float* bk    = (const float*)d_in[4];
    const float* wv    = (const float*)d_in[5];
    const float* bv    = (const float*)d_in[6];
    const float* gamma = (const float*)d_in[7];
    float* out = (float*)d_out;

    static bool attr_done = false;
    if (!attr_done) {
        cudaFuncSetAttribute(qk_kxt_kernel, cudaFuncAttributeMaxDynamicSharedMemorySize,
                             SMEM_TOT);
        cudaFuncSetAttribute(out_kernel, cudaFuncAttributeMaxDynamicSharedMemorySize,
                             O_SMEM);
        attr_done = true;
    }

    init_kernel<<<(BATCH * DD * CH + 255) / 256, 256>>>(wq, wk);
    qk_kxt_kernel<<<dim3(NN / 128, BATCH), 256, SMEM_TOT>>>(x, bq, bk);
    norm_kernel<<<dim3(NN / 256, BATCH), 256>>>();
    kv_kernel<<<dim3(CH / 128, (BATCH * DD) / 64, 16), 256>>>(wv, bv);
    kvt_kernel<<<dim3(CH / 128, BATCH), 256>>>();
    out_kernel<<<dim3(NN / 128, CH / 128, BATCH), 256, O_SMEM>>>(x, gamma, out);
}